// round 3
// baseline (speedup 1.0000x reference)
#include <cuda_runtime.h>
#include <cstdint>

#define N_NODES 50000
#define N_EDGES 800000
#define F 64

// Scratch (allocation-free: __device__ globals)
__device__ float g_s[N_NODES * F];    // neighbor-sum accumulator
__device__ float g_cnt[N_NODES];      // in-degree counts
__device__ float g_h[N_NODES * F];    // hidden activations after layer 1
__device__ int   g_is64;              // 1 if edge_index is int64, 0 if int32

// ---------------------------------------------------------------------------
// Detect edge_index dtype. int32 data misread as int64 puts the NEXT random
// index in the high 32 bits -> value >= 2^32 almost surely. Deterministic.
// ---------------------------------------------------------------------------
__global__ void detect_kernel(const void* __restrict__ ei) {
    const long long* p64 = (const long long*)ei;
    int ok = 1;
    #pragma unroll
    for (int i = 0; i < 16; i++) {
        long long v = p64[i];
        if (v < 0 || v >= N_NODES) ok = 0;
    }
    g_is64 = ok;
}

// ---------------------------------------------------------------------------
// Zero the accumulator (and counts on the first pass)
// ---------------------------------------------------------------------------
__global__ void zero_kernel(int zero_cnt) {
    int i = blockIdx.x * blockDim.x + threadIdx.x;
    if (i < N_NODES * F / 4)
        reinterpret_cast<float4*>(g_s)[i] = make_float4(0.f, 0.f, 0.f, 0.f);
    if (zero_cnt && i < N_NODES)
        g_cnt[i] = 0.f;
}

__device__ __forceinline__ int load_idx(const void* ei, int i, int is64) {
    if (is64) return (int)((const long long*)ei)[i];
    return ((const int*)ei)[i];
}

// ---------------------------------------------------------------------------
// Scatter: 16 threads per edge, each thread owns one float4 (4 of 64 feats).
// Gather is coalesced (16 consecutive float4 = two 128B lines per row).
// Reduction: scalar atomicAdd, result unused -> REDG.E.ADD.F32.
// ---------------------------------------------------------------------------
__global__ void scatter_kernel(const float* __restrict__ xin_ext,
                               const void* __restrict__ ei,
                               int do_cnt, int from_gh) {
    const float* xin = from_gh ? g_h : xin_ext;
    long long gid = (long long)blockIdx.x * blockDim.x + threadIdx.x;
    int e = (int)(gid >> 4);
    if (e >= N_EDGES) return;
    int p = (int)(gid & 15);

    int is64 = g_is64;
    int s = load_idx(ei, e, is64);
    int d = load_idx(ei, N_EDGES + e, is64);
    if ((unsigned)s >= N_NODES || (unsigned)d >= N_NODES) return;  // trap guard

    float4 v = reinterpret_cast<const float4*>(xin)[s * 16 + p];
    float* base = g_s + d * 64 + p * 4;
    atomicAdd(base + 0, v.x);
    atomicAdd(base + 1, v.y);
    atomicAdd(base + 2, v.z);
    atomicAdd(base + 3, v.w);

    if (do_cnt && p == 0) {
        atomicAdd(&g_cnt[d], 1.0f);
    }
}

// ---------------------------------------------------------------------------
// Fused concat + GEMM + bias (+ReLU):
//   out[n, c] = relu( sum_k [x[n] || s[n]/max(cnt,1)]_k * W[k, c] + b[c] )
// Block: 512 threads = 8 nodes x 64 output columns. W staged in SMEM (32 KB).
// ---------------------------------------------------------------------------
__global__ void __launch_bounds__(512)
sage_linear_kernel(const float* __restrict__ xin_ext,
                   const float* __restrict__ W,
                   const float* __restrict__ b,
                   float* __restrict__ out_ext,
                   int relu, int from_gh, int to_gh) {
    __shared__ float Ws[128 * 64];
    __shared__ float row[8][128];

    const float* xin = from_gh ? g_h : xin_ext;
    float* out = to_gh ? g_h : out_ext;

    int tid = threadIdx.x;
    #pragma unroll
    for (int i = 0; i < 16; i++)
        Ws[tid + i * 512] = W[tid + i * 512];

    int out_c = tid & 63;
    int ln = tid >> 6;           // local node 0..7
    int base = blockIdx.x * 8;   // 6250 blocks * 8 = 50000 exactly

    // Cooperative load of 8 node rows: [x(64) || mean_agg(64)]
    #pragma unroll
    for (int it = 0; it < 2; it++) {
        int j = tid + it * 512;
        int node = j >> 7;       // 0..7
        int k = j & 127;
        int n = base + node;
        float v;
        if (k < 64) {
            v = xin[n * 64 + k];
        } else {
            float c = g_cnt[n];
            v = g_s[n * 64 + (k - 64)] / fmaxf(c, 1.0f);
        }
        row[node][k] = v;
    }
    __syncthreads();

    int n = base + ln;
    float acc = b[out_c];
    #pragma unroll
    for (int k = 0; k < 128; k++)
        acc = fmaf(row[ln][k], Ws[k * 64 + out_c], acc);

    if (relu) acc = fmaxf(acc, 0.f);
    out[n * 64 + out_c] = acc;
}

// ---------------------------------------------------------------------------
// Launch: two SAGE layers. All graph-capturable, no syncs, no allocations.
// ---------------------------------------------------------------------------
extern "C" void kernel_launch(void* const* d_in, const int* in_sizes, int n_in,
                              void* d_out, int out_size) {
    const float* x   = (const float*)d_in[0];
    const void*  ei  = d_in[1];
    const float* W1  = (const float*)d_in[2];
    const float* b1  = (const float*)d_in[3];
    const float* W2  = (const float*)d_in[4];
    const float* b2  = (const float*)d_in[5];
    float*       out = (float*)d_out;

    const int ZERO_BLOCKS    = (N_NODES * F / 4 + 255) / 256;   // 3125
    const int SCATTER_BLOCKS = (N_EDGES * 16 + 255) / 256;      // 50000
    const int LINEAR_BLOCKS  = N_NODES / 8;                     // 6250

    detect_kernel<<<1, 1>>>(ei);

    // Layer 1
    zero_kernel<<<ZERO_BLOCKS, 256>>>(1);
    scatter_kernel<<<SCATTER_BLOCKS, 256>>>(x, ei, /*do_cnt=*/1, /*from_gh=*/0);
    sage_linear_kernel<<<LINEAR_BLOCKS, 512>>>(x, W1, b1, nullptr,
                                               /*relu=*/1, /*from_gh=*/0, /*to_gh=*/1);
    // Layer 2
    zero_kernel<<<ZERO_BLOCKS, 256>>>(0);
    scatter_kernel<<<SCATTER_BLOCKS, 256>>>(nullptr, ei, /*do_cnt=*/0, /*from_gh=*/1);
    sage_linear_kernel<<<LINEAR_BLOCKS, 512>>>(nullptr, W2, b2, out,
                                               /*relu=*/0, /*from_gh=*/1, /*to_gh=*/0);
}

// round 4
// speedup vs baseline: 1.8200x; 1.8200x over previous
#include <cuda_runtime.h>
#include <cstdint>

#define N_NODES 50000
#define N_EDGES 800000
#define F 64
#define NPB 32            // nodes per block in linear kernel
#define ROW_PAD 132       // 128 + 4 pad (float4-aligned, bank-shifted)

// Scratch (allocation-free: __device__ globals)
__device__ float g_s[N_NODES * F];    // neighbor-sum accumulator
__device__ float g_cnt[N_NODES];      // in-degree counts
__device__ float g_h[N_NODES * F];    // hidden activations after layer 1
__device__ int   g_is64;              // 1 if edge_index is int64, 0 if int32

// ---------------------------------------------------------------------------
// Detect edge_index dtype (int64 vs int32-narrowed). Deterministic.
// ---------------------------------------------------------------------------
__global__ void detect_kernel(const void* __restrict__ ei) {
    const long long* p64 = (const long long*)ei;
    int ok = 1;
    #pragma unroll
    for (int i = 0; i < 16; i++) {
        long long v = p64[i];
        if (v < 0 || v >= N_NODES) ok = 0;
    }
    g_is64 = ok;
}

__global__ void zero_kernel(int zero_cnt) {
    int i = blockIdx.x * blockDim.x + threadIdx.x;
    if (i < N_NODES * F / 4)
        reinterpret_cast<float4*>(g_s)[i] = make_float4(0.f, 0.f, 0.f, 0.f);
    if (zero_cnt && i < N_NODES)
        g_cnt[i] = 0.f;
}

__device__ __forceinline__ int load_idx(const void* ei, int i, int is64) {
    if (is64) return (int)((const long long*)ei)[i];
    return ((const int*)ei)[i];
}

// ---------------------------------------------------------------------------
// Scatter: 16 threads/edge, one float4 each. Indices loaded once per edge
// (lane 0 / lane 16) and shuffled. Vector RED: red.global.add.v4.f32 ->
// 1 L2 reduction transaction per thread instead of 4.
// ---------------------------------------------------------------------------
__global__ void scatter_kernel(const float* __restrict__ xin_ext,
                               const void* __restrict__ ei,
                               int do_cnt, int from_gh) {
    const float* xin = from_gh ? g_h : xin_ext;
    long long gid = (long long)blockIdx.x * blockDim.x + threadIdx.x;
    int e = (int)(gid >> 4);
    if (e >= N_EDGES) return;
    int p = (int)(gid & 15);
    int lane = threadIdx.x & 31;

    int is64 = g_is64;
    int s = 0, d = 0;
    if ((lane & 15) == 0) {
        s = load_idx(ei, e, is64);
        d = load_idx(ei, N_EDGES + e, is64);
    }
    s = __shfl_sync(0xffffffffu, s, lane & 16);
    d = __shfl_sync(0xffffffffu, d, lane & 16);
    if ((unsigned)s >= N_NODES || (unsigned)d >= N_NODES) return;  // trap guard

    float4 v = reinterpret_cast<const float4*>(xin)[s * 16 + p];
    float4* addr = reinterpret_cast<float4*>(g_s) + d * 16 + p;
    unsigned long long gaddr = (unsigned long long)__cvta_generic_to_global(addr);
    asm volatile("red.global.add.v4.f32 [%0], {%1, %2, %3, %4};"
                 :: "l"(gaddr), "f"(v.x), "f"(v.y), "f"(v.z), "f"(v.w)
                 : "memory");

    if (do_cnt && p == 0) {
        atomicAdd(&g_cnt[d], 1.0f);
    }
}

// ---------------------------------------------------------------------------
// Fused concat + GEMM + bias (+ReLU), register-tiled:
// 512 threads = 32 nodes x 16 col-groups; each thread computes a float4 of
// outputs. Per k: 1 broadcast LDS (row) + 1 LDS.128 (W) -> 4 FFMA.
// ---------------------------------------------------------------------------
__global__ void __launch_bounds__(512)
sage_linear_kernel(const float* __restrict__ xin_ext,
                   const float* __restrict__ W,
                   const float* __restrict__ b,
                   float* __restrict__ out_ext,
                   int relu, int from_gh, int to_gh) {
    __shared__ float4 Ws4[128 * 16];        // W as [k][col-group] float4, 32KB
    __shared__ float  row[NPB][ROW_PAD];    // [x || mean_agg], padded

    const float* xin = from_gh ? g_h : xin_ext;
    float* out = to_gh ? g_h : out_ext;

    int tid = threadIdx.x;
    // Stage W: 128*16 = 2048 float4, 4 per thread.
    const float4* W4 = reinterpret_cast<const float4*>(W);
    #pragma unroll
    for (int i = 0; i < 4; i++)
        Ws4[tid + i * 512] = W4[tid + i * 512];

    int ln = tid >> 4;          // local node 0..31
    int q  = tid & 15;          // float4 group 0..15
    int base = blockIdx.x * NPB;
    int n = base + ln;
    int nc = n < N_NODES ? n : N_NODES - 1;   // clamped for loads

    // Stage rows: x half and mean-agg half, one float4 each per thread.
    {
        float4 xv = reinterpret_cast<const float4*>(xin)[nc * 16 + q];
        *reinterpret_cast<float4*>(&row[ln][q * 4]) = xv;

        float c = fmaxf(g_cnt[nc], 1.0f);
        float inv = 1.0f / c;
        float4 sv = reinterpret_cast<const float4*>(g_s)[nc * 16 + q];
        sv.x *= inv; sv.y *= inv; sv.z *= inv; sv.w *= inv;
        *reinterpret_cast<float4*>(&row[ln][64 + q * 4]) = sv;
    }
    __syncthreads();

    float4 bv = reinterpret_cast<const float4*>(b)[q];
    float4 acc = bv;
    #pragma unroll 16
    for (int k = 0; k < 128; k++) {
        float rv = row[ln][k];
        float4 w = Ws4[k * 16 + q];
        acc.x = fmaf(rv, w.x, acc.x);
        acc.y = fmaf(rv, w.y, acc.y);
        acc.z = fmaf(rv, w.z, acc.z);
        acc.w = fmaf(rv, w.w, acc.w);
    }

    if (relu) {
        acc.x = fmaxf(acc.x, 0.f); acc.y = fmaxf(acc.y, 0.f);
        acc.z = fmaxf(acc.z, 0.f); acc.w = fmaxf(acc.w, 0.f);
    }
    if (n < N_NODES)
        reinterpret_cast<float4*>(out)[n * 16 + q] = acc;
}

// ---------------------------------------------------------------------------
// Launch: two SAGE layers. All graph-capturable, no syncs, no allocations.
// ---------------------------------------------------------------------------
extern "C" void kernel_launch(void* const* d_in, const int* in_sizes, int n_in,
                              void* d_out, int out_size) {
    const float* x   = (const float*)d_in[0];
    const void*  ei  = d_in[1];
    const float* W1  = (const float*)d_in[2];
    const float* b1  = (const float*)d_in[3];
    const float* W2  = (const float*)d_in[4];
    const float* b2  = (const float*)d_in[5];
    float*       out = (float*)d_out;

    const int ZERO_BLOCKS    = (N_NODES * F / 4 + 255) / 256;   // 3125
    const int SCATTER_BLOCKS = (N_EDGES * 16 + 255) / 256;      // 50000
    const int LINEAR_BLOCKS  = (N_NODES + NPB - 1) / NPB;       // 1563

    detect_kernel<<<1, 1>>>(ei);

    // Layer 1
    zero_kernel<<<ZERO_BLOCKS, 256>>>(1);
    scatter_kernel<<<SCATTER_BLOCKS, 256>>>(x, ei, /*do_cnt=*/1, /*from_gh=*/0);
    sage_linear_kernel<<<LINEAR_BLOCKS, 512>>>(x, W1, b1, nullptr,
                                               /*relu=*/1, /*from_gh=*/0, /*to_gh=*/1);
    // Layer 2
    zero_kernel<<<ZERO_BLOCKS, 256>>>(0);
    scatter_kernel<<<SCATTER_BLOCKS, 256>>>(nullptr, ei, /*do_cnt=*/0, /*from_gh=*/1);
    sage_linear_kernel<<<LINEAR_BLOCKS, 512>>>(nullptr, W2, b2, out,
                                               /*relu=*/0, /*from_gh=*/1, /*to_gh=*/0);
}

// round 5
// speedup vs baseline: 2.4965x; 1.3717x over previous
#include <cuda_runtime.h>
#include <cstdint>

#define N_NODES 50000
#define N_EDGES 800000
#define F 64
#define TILE_N 64                  // nodes per block (linear kernel)
#define ROWT_STRIDE 17             // float4 stride of rowT (68 floats, padded)

// Scratch (allocation-free: __device__ globals)
__device__ float g_s[N_NODES * F];    // neighbor-sum accumulator
__device__ float g_cnt[N_NODES];      // in-degree counts
__device__ float g_h[N_NODES * F];    // hidden activations after layer 1
__device__ int   g_is64;              // 1 if edge_index is int64, 0 if int32

// ---------------------------------------------------------------------------
// Detect edge_index dtype (int64 vs int32-narrowed). Deterministic.
// ---------------------------------------------------------------------------
__global__ void detect_kernel(const void* __restrict__ ei) {
    const long long* p64 = (const long long*)ei;
    int ok = 1;
    #pragma unroll
    for (int i = 0; i < 16; i++) {
        long long v = p64[i];
        if (v < 0 || v >= N_NODES) ok = 0;
    }
    g_is64 = ok;
}

__global__ void zero_kernel(int zero_cnt) {
    int i = blockIdx.x * blockDim.x + threadIdx.x;
    if (i < N_NODES * F / 4)
        reinterpret_cast<float4*>(g_s)[i] = make_float4(0.f, 0.f, 0.f, 0.f);
    if (zero_cnt && i < N_NODES)
        g_cnt[i] = 0.f;
}

__device__ __forceinline__ int load_idx(const void* ei, int i, int is64) {
    if (is64) return (int)((const long long*)ei)[i];
    return ((const int*)ei)[i];
}

// ---------------------------------------------------------------------------
// Scatter: 16 threads/edge, one float4 each. Indices loaded once per edge
// (lane 0 / lane 16) and shuffled. Vector RED: red.global.add.v4.f32.
// ---------------------------------------------------------------------------
__global__ void scatter_kernel(const float* __restrict__ xin_ext,
                               const void* __restrict__ ei,
                               int do_cnt, int from_gh) {
    const float* xin = from_gh ? g_h : xin_ext;
    long long gid = (long long)blockIdx.x * blockDim.x + threadIdx.x;
    int e = (int)(gid >> 4);
    if (e >= N_EDGES) return;
    int p = (int)(gid & 15);
    int lane = threadIdx.x & 31;

    int is64 = g_is64;
    int s = 0, d = 0;
    if ((lane & 15) == 0) {
        s = load_idx(ei, e, is64);
        d = load_idx(ei, N_EDGES + e, is64);
    }
    s = __shfl_sync(0xffffffffu, s, lane & 16);
    d = __shfl_sync(0xffffffffu, d, lane & 16);
    if ((unsigned)s >= N_NODES || (unsigned)d >= N_NODES) return;  // trap guard

    float4 v = reinterpret_cast<const float4*>(xin)[s * 16 + p];
    float4* addr = reinterpret_cast<float4*>(g_s) + d * 16 + p;
    unsigned long long gaddr = (unsigned long long)__cvta_generic_to_global(addr);
    asm volatile("red.global.add.v4.f32 [%0], {%1, %2, %3, %4};"
                 :: "l"(gaddr), "f"(v.x), "f"(v.y), "f"(v.z), "f"(v.w)
                 : "memory");

    if (do_cnt && p == 0) {
        atomicAdd(&g_cnt[d], 1.0f);
    }
}

// ---------------------------------------------------------------------------
// Fused concat + GEMM + bias (+ReLU), SGEMM-style register tiling:
//   block = 256 threads -> 64 nodes x 64 cols tile, K = 128
//   thread tile = 4 nodes x 4 cols (float4), 16 accumulators
//   rowT stored k-major ([k][node]) so the A-load is a 2-address LDS.128;
//   W row load is one LDS.128 per thread (full 64-col row per warp).
// Dynamic smem: Ws4 (32 KB) + rowT (34 KB) = 66.8 KB.
// ---------------------------------------------------------------------------
__global__ void __launch_bounds__(256)
sage_linear_kernel(const float* __restrict__ xin_ext,
                   const float* __restrict__ W,
                   const float* __restrict__ b,
                   float* __restrict__ out_ext,
                   int relu, int from_gh, int to_gh) {
    extern __shared__ float smem[];
    float4* Ws4  = reinterpret_cast<float4*>(smem);          // [128][16] float4
    float4* rowT = reinterpret_cast<float4*>(smem) + 128*16; // [128][ROWT_STRIDE] float4

    const float* xin = from_gh ? g_h : xin_ext;
    float* out = to_gh ? g_h : out_ext;

    int tid = threadIdx.x;

    // Stage W: 2048 float4, 8 per thread.
    const float4* W4 = reinterpret_cast<const float4*>(W);
    #pragma unroll
    for (int i = 0; i < 8; i++)
        Ws4[tid + i * 256] = W4[tid + i * 256];

    int base = blockIdx.x * TILE_N;

    // Stage rows transposed. Thread: node_l = tid>>2 (0..63), kq = tid&3.
    // Loads 4 float4 of x (q = kq+4i) and 4 float4 of agg; stores scalars
    // into rowT[k][node_l].
    {
        int node_l = tid >> 2;
        int kq = tid & 3;
        int n = base + node_l;
        int nc = n < N_NODES ? n : N_NODES - 1;
        float inv = 1.0f / fmaxf(g_cnt[nc], 1.0f);
        float* rowTf = reinterpret_cast<float*>(rowT);
        #pragma unroll
        for (int i = 0; i < 4; i++) {
            int q = kq + 4 * i;                    // 0..15
            float4 xv = reinterpret_cast<const float4*>(xin)[nc * 16 + q];
            rowTf[(q * 4 + 0) * (ROWT_STRIDE*4) + node_l] = xv.x;
            rowTf[(q * 4 + 1) * (ROWT_STRIDE*4) + node_l] = xv.y;
            rowTf[(q * 4 + 2) * (ROWT_STRIDE*4) + node_l] = xv.z;
            rowTf[(q * 4 + 3) * (ROWT_STRIDE*4) + node_l] = xv.w;

            float4 sv = reinterpret_cast<const float4*>(g_s)[nc * 16 + q];
            rowTf[(64 + q * 4 + 0) * (ROWT_STRIDE*4) + node_l] = sv.x * inv;
            rowTf[(64 + q * 4 + 1) * (ROWT_STRIDE*4) + node_l] = sv.y * inv;
            rowTf[(64 + q * 4 + 2) * (ROWT_STRIDE*4) + node_l] = sv.z * inv;
            rowTf[(64 + q * 4 + 3) * (ROWT_STRIDE*4) + node_l] = sv.w * inv;
        }
    }
    __syncthreads();

    int tx = tid & 15;          // col float4 group 0..15
    int ty = tid >> 4;          // node group 0..15 (4 nodes each)

    float4 bv = reinterpret_cast<const float4*>(b)[tx];
    float4 acc0 = bv, acc1 = bv, acc2 = bv, acc3 = bv;

    #pragma unroll 8
    for (int k = 0; k < 128; k++) {
        float4 a = rowT[k * ROWT_STRIDE + ty];     // 4 nodes' values at k
        float4 w = Ws4[k * 16 + tx];               // 4 cols' weights at k
        acc0.x = fmaf(a.x, w.x, acc0.x); acc0.y = fmaf(a.x, w.y, acc0.y);
        acc0.z = fmaf(a.x, w.z, acc0.z); acc0.w = fmaf(a.x, w.w, acc0.w);
        acc1.x = fmaf(a.y, w.x, acc1.x); acc1.y = fmaf(a.y, w.y, acc1.y);
        acc1.z = fmaf(a.y, w.z, acc1.z); acc1.w = fmaf(a.y, w.w, acc1.w);
        acc2.x = fmaf(a.z, w.x, acc2.x); acc2.y = fmaf(a.z, w.y, acc2.y);
        acc2.z = fmaf(a.z, w.z, acc2.z); acc2.w = fmaf(a.z, w.w, acc2.w);
        acc3.x = fmaf(a.w, w.x, acc3.x); acc3.y = fmaf(a.w, w.y, acc3.y);
        acc3.z = fmaf(a.w, w.z, acc3.z); acc3.w = fmaf(a.w, w.w, acc3.w);
    }

    if (relu) {
        acc0.x = fmaxf(acc0.x, 0.f); acc0.y = fmaxf(acc0.y, 0.f);
        acc0.z = fmaxf(acc0.z, 0.f); acc0.w = fmaxf(acc0.w, 0.f);
        acc1.x = fmaxf(acc1.x, 0.f); acc1.y = fmaxf(acc1.y, 0.f);
        acc1.z = fmaxf(acc1.z, 0.f); acc1.w = fmaxf(acc1.w, 0.f);
        acc2.x = fmaxf(acc2.x, 0.f); acc2.y = fmaxf(acc2.y, 0.f);
        acc2.z = fmaxf(acc2.z, 0.f); acc2.w = fmaxf(acc2.w, 0.f);
        acc3.x = fmaxf(acc3.x, 0.f); acc3.y = fmaxf(acc3.y, 0.f);
        acc3.z = fmaxf(acc3.z, 0.f); acc3.w = fmaxf(acc3.w, 0.f);
    }

    int n0 = base + ty * 4;
    float4* out4 = reinterpret_cast<float4*>(out);
    if (n0 + 0 < N_NODES) out4[(n0 + 0) * 16 + tx] = acc0;
    if (n0 + 1 < N_NODES) out4[(n0 + 1) * 16 + tx] = acc1;
    if (n0 + 2 < N_NODES) out4[(n0 + 2) * 16 + tx] = acc2;
    if (n0 + 3 < N_NODES) out4[(n0 + 3) * 16 + tx] = acc3;
}

// ---------------------------------------------------------------------------
// Launch: two SAGE layers. All graph-capturable, no syncs, no allocations.
// ---------------------------------------------------------------------------
extern "C" void kernel_launch(void* const* d_in, const int* in_sizes, int n_in,
                              void* d_out, int out_size) {
    const float* x   = (const float*)d_in[0];
    const void*  ei  = d_in[1];
    const float* W1  = (const float*)d_in[2];
    const float* b1  = (const float*)d_in[3];
    const float* W2  = (const float*)d_in[4];
    const float* b2  = (const float*)d_in[5];
    float*       out = (float*)d_out;

    const int ZERO_BLOCKS    = (N_NODES * F / 4 + 255) / 256;       // 3125
    const int SCATTER_BLOCKS = (N_EDGES * 16 + 255) / 256;          // 50000
    const int LINEAR_BLOCKS  = (N_NODES + TILE_N - 1) / TILE_N;     // 782
    const int SMEM_BYTES     = (128 * 16 + 128 * ROWT_STRIDE) * 16; // 67584

    cudaFuncSetAttribute(sage_linear_kernel,
                         cudaFuncAttributeMaxDynamicSharedMemorySize, SMEM_BYTES);

    detect_kernel<<<1, 1>>>(ei);

    // Layer 1
    zero_kernel<<<ZERO_BLOCKS, 256>>>(1);
    scatter_kernel<<<SCATTER_BLOCKS, 256>>>(x, ei, /*do_cnt=*/1, /*from_gh=*/0);
    sage_linear_kernel<<<LINEAR_BLOCKS, 256, SMEM_BYTES>>>(x, W1, b1, nullptr,
                                               /*relu=*/1, /*from_gh=*/0, /*to_gh=*/1);
    // Layer 2
    zero_kernel<<<ZERO_BLOCKS, 256>>>(0);
    scatter_kernel<<<SCATTER_BLOCKS, 256>>>(nullptr, ei, /*do_cnt=*/0, /*from_gh=*/1);
    sage_linear_kernel<<<LINEAR_BLOCKS, 256, SMEM_BYTES>>>(nullptr, W2, b2, out,
                                               /*relu=*/0, /*from_gh=*/1, /*to_gh=*/0);
}

// round 6
// speedup vs baseline: 2.6521x; 1.0623x over previous
#include <cuda_runtime.h>
#include <cstdint>

#define N_NODES 50000
#define N_EDGES 800000
#define F 64
#define TILE_N 64
#define ROWT_STRIDE 17             // float4 stride of rowT (68 floats)
#define SCAN_BLOCKS 196            // ceil(50000/256)

// Scratch (allocation-free: __device__ globals)
__device__ int   g_deg[N_NODES];
__device__ int   g_off[N_NODES + 1];
__device__ int   g_cur[N_NODES];
__device__ int   g_csr[N_EDGES];       // src indices bucketed by dst
__device__ int   g_bsum[SCAN_BLOCKS];
__device__ float g_h[N_NODES * F];     // hidden activations after layer 1
__device__ int   g_is64;               // 1 if edge_index int64, 0 if int32

// ---------------------------------------------------------------------------
__global__ void detect_kernel(const void* __restrict__ ei) {
    const long long* p64 = (const long long*)ei;
    int ok = 1;
    #pragma unroll
    for (int i = 0; i < 16; i++) {
        long long v = p64[i];
        if (v < 0 || v >= N_NODES) ok = 0;
    }
    g_is64 = ok;
}

__device__ __forceinline__ int load_idx(const void* ei, int i, int is64) {
    if (is64) return (int)((const long long*)ei)[i];
    return ((const int*)ei)[i];
}

// ---------------------------------------------------------------------------
// CSR build: zero -> histogram -> 3-step scan -> fill
// ---------------------------------------------------------------------------
__global__ void zero_deg_kernel() {
    int i = blockIdx.x * blockDim.x + threadIdx.x;
    if (i < N_NODES) g_deg[i] = 0;
}

__global__ void hist_kernel(const void* __restrict__ ei) {
    int e = blockIdx.x * blockDim.x + threadIdx.x;
    if (e >= N_EDGES) return;
    int d = load_idx(ei, N_EDGES + e, g_is64);
    if ((unsigned)d < N_NODES) atomicAdd(&g_deg[d], 1);
}

__global__ void scan1_kernel() {
    __shared__ int sh[256];
    int t = threadIdx.x;
    int i = blockIdx.x * 256 + t;
    int v = (i < N_NODES) ? g_deg[i] : 0;
    sh[t] = v;
    __syncthreads();
    #pragma unroll
    for (int ofs = 1; ofs < 256; ofs <<= 1) {
        int add = (t >= ofs) ? sh[t - ofs] : 0;
        __syncthreads();
        sh[t] += add;
        __syncthreads();
    }
    if (i < N_NODES) g_off[i + 1] = sh[t];
    if (t == 255) g_bsum[blockIdx.x] = sh[255];
}

__global__ void scan2_kernel() {
    __shared__ int sh[256];
    int t = threadIdx.x;
    sh[t] = (t < SCAN_BLOCKS) ? g_bsum[t] : 0;
    __syncthreads();
    #pragma unroll
    for (int ofs = 1; ofs < 256; ofs <<= 1) {
        int add = (t >= ofs) ? sh[t - ofs] : 0;
        __syncthreads();
        sh[t] += add;
        __syncthreads();
    }
    if (t < SCAN_BLOCKS) g_bsum[t] = sh[t];
}

__global__ void scan3_kernel() {
    int t = threadIdx.x;
    int i = blockIdx.x * 256 + t;
    if (i < N_NODES) {
        if (blockIdx.x > 0) g_off[i + 1] += g_bsum[blockIdx.x - 1];
        g_cur[i] = 0;
    }
    if (i == 0) g_off[0] = 0;
}

__global__ void fill_kernel(const void* __restrict__ ei) {
    int e = blockIdx.x * blockDim.x + threadIdx.x;
    if (e >= N_EDGES) return;
    int is64 = g_is64;
    int s = load_idx(ei, e, is64);
    int d = load_idx(ei, N_EDGES + e, is64);
    if ((unsigned)s >= N_NODES || (unsigned)d >= N_NODES) return;
    int pos = atomicAdd(&g_cur[d], 1);
    g_csr[g_off[d] + pos] = s;
}

// ---------------------------------------------------------------------------
// Fused SAGE layer: CSR mean-aggregation + concat + GEMM + bias (+ReLU).
// Block = 256 threads, 64-node tile.
//   Phase A: stage x transposed (k 0..63) + warp-per-node CSR gather-mean
//            into rowT (k 64..127).
//   Phase B: SGEMM register tiling, thread tile 4x4 (16 accums).
// Dynamic smem: Ws4 32KB + rowT 34.8KB = 66.8KB.
// ---------------------------------------------------------------------------
__global__ void __launch_bounds__(256)
sage_fused_kernel(const float* __restrict__ xin_ext,
                  const float* __restrict__ W,
                  const float* __restrict__ b,
                  float* __restrict__ out_ext,
                  int relu, int from_gh, int to_gh) {
    extern __shared__ float smem[];
    float4* Ws4  = reinterpret_cast<float4*>(smem);            // [128][16] f4
    float4* rowT = reinterpret_cast<float4*>(smem) + 128 * 16; // [128][17] f4
    float*  rowTf = reinterpret_cast<float*>(rowT);

    const float* xin = from_gh ? g_h : xin_ext;
    float* out = to_gh ? g_h : out_ext;

    int tid = threadIdx.x;
    const float4* W4 = reinterpret_cast<const float4*>(W);
    #pragma unroll
    for (int i = 0; i < 8; i++)
        Ws4[tid + i * 256] = W4[tid + i * 256];

    int base = blockIdx.x * TILE_N;

    // Phase A1: stage x transposed into k = 0..63
    {
        int node_l = tid >> 2;
        int kq = tid & 3;
        int n = base + node_l;
        int nc = n < N_NODES ? n : N_NODES - 1;
        #pragma unroll
        for (int i = 0; i < 4; i++) {
            int q = kq * 4 + i;   // 0..15
            float4 xv = reinterpret_cast<const float4*>(xin)[nc * 16 + q];
            rowTf[(q * 4 + 0) * (ROWT_STRIDE * 4) + node_l] = xv.x;
            rowTf[(q * 4 + 1) * (ROWT_STRIDE * 4) + node_l] = xv.y;
            rowTf[(q * 4 + 2) * (ROWT_STRIDE * 4) + node_l] = xv.z;
            rowTf[(q * 4 + 3) * (ROWT_STRIDE * 4) + node_l] = xv.w;
        }
    }

    // Phase A2: warp-per-node CSR gather + mean into k = 64..127
    {
        int w = tid >> 5, lane = tid & 31;
        const float2* xin2 = reinterpret_cast<const float2*>(xin);
        #pragma unroll 1
        for (int i = 0; i < 8; i++) {
            int node_l = w * 8 + i;
            int n = base + node_l;
            float ax = 0.f, ay = 0.f;
            int deg = 0;
            if (n < N_NODES) {
                int e0 = g_off[n], e1 = g_off[n + 1];
                deg = e1 - e0;
                int e = e0;
                for (; e + 2 <= e1; e += 2) {      // unroll-2 for MLP
                    int s0 = g_csr[e];
                    int s1 = g_csr[e + 1];
                    float2 v0 = xin2[s0 * 32 + lane];
                    float2 v1 = xin2[s1 * 32 + lane];
                    ax += v0.x; ay += v0.y;
                    ax += v1.x; ay += v1.y;
                }
                if (e < e1) {
                    int s0 = g_csr[e];
                    float2 v = xin2[s0 * 32 + lane];
                    ax += v.x; ay += v.y;
                }
            }
            float inv = 1.0f / fmaxf((float)deg, 1.0f);
            rowTf[(64 + 2 * lane + 0) * (ROWT_STRIDE * 4) + node_l] = ax * inv;
            rowTf[(64 + 2 * lane + 1) * (ROWT_STRIDE * 4) + node_l] = ay * inv;
        }
    }
    __syncthreads();

    // Phase B: GEMM, thread tile 4 nodes x 4 cols
    int tx = tid & 15;
    int ty = tid >> 4;

    float4 bv = reinterpret_cast<const float4*>(b)[tx];
    float4 acc0 = bv, acc1 = bv, acc2 = bv, acc3 = bv;

    #pragma unroll 8
    for (int k = 0; k < 128; k++) {
        float4 a = rowT[k * ROWT_STRIDE + ty];
        float4 w = Ws4[k * 16 + tx];
        acc0.x = fmaf(a.x, w.x, acc0.x); acc0.y = fmaf(a.x, w.y, acc0.y);
        acc0.z = fmaf(a.x, w.z, acc0.z); acc0.w = fmaf(a.x, w.w, acc0.w);
        acc1.x = fmaf(a.y, w.x, acc1.x); acc1.y = fmaf(a.y, w.y, acc1.y);
        acc1.z = fmaf(a.y, w.z, acc1.z); acc1.w = fmaf(a.y, w.w, acc1.w);
        acc2.x = fmaf(a.z, w.x, acc2.x); acc2.y = fmaf(a.z, w.y, acc2.y);
        acc2.z = fmaf(a.z, w.z, acc2.z); acc2.w = fmaf(a.z, w.w, acc2.w);
        acc3.x = fmaf(a.w, w.x, acc3.x); acc3.y = fmaf(a.w, w.y, acc3.y);
        acc3.z = fmaf(a.w, w.z, acc3.z); acc3.w = fmaf(a.w, w.w, acc3.w);
    }

    if (relu) {
        acc0.x = fmaxf(acc0.x, 0.f); acc0.y = fmaxf(acc0.y, 0.f);
        acc0.z = fmaxf(acc0.z, 0.f); acc0.w = fmaxf(acc0.w, 0.f);
        acc1.x = fmaxf(acc1.x, 0.f); acc1.y = fmaxf(acc1.y, 0.f);
        acc1.z = fmaxf(acc1.z, 0.f); acc1.w = fmaxf(acc1.w, 0.f);
        acc2.x = fmaxf(acc2.x, 0.f); acc2.y = fmaxf(acc2.y, 0.f);
        acc2.z = fmaxf(acc2.z, 0.f); acc2.w = fmaxf(acc2.w, 0.f);
        acc3.x = fmaxf(acc3.x, 0.f); acc3.y = fmaxf(acc3.y, 0.f);
        acc3.z = fmaxf(acc3.z, 0.f); acc3.w = fmaxf(acc3.w, 0.f);
    }

    int n0 = base + ty * 4;
    float4* out4 = reinterpret_cast<float4*>(out);
    if (n0 + 0 < N_NODES) out4[(n0 + 0) * 16 + tx] = acc0;
    if (n0 + 1 < N_NODES) out4[(n0 + 1) * 16 + tx] = acc1;
    if (n0 + 2 < N_NODES) out4[(n0 + 2) * 16 + tx] = acc2;
    if (n0 + 3 < N_NODES) out4[(n0 + 3) * 16 + tx] = acc3;
}

// ---------------------------------------------------------------------------
extern "C" void kernel_launch(void* const* d_in, const int* in_sizes, int n_in,
                              void* d_out, int out_size) {
    const float* x   = (const float*)d_in[0];
    const void*  ei  = d_in[1];
    const float* W1  = (const float*)d_in[2];
    const float* b1  = (const float*)d_in[3];
    const float* W2  = (const float*)d_in[4];
    const float* b2  = (const float*)d_in[5];
    float*       out = (float*)d_out;

    const int EDGE_BLOCKS   = (N_EDGES + 255) / 256;              // 3125
    const int LINEAR_BLOCKS = (N_NODES + TILE_N - 1) / TILE_N;    // 782
    const int SMEM_BYTES    = (128 * 16 + 128 * ROWT_STRIDE) * 16; // 67584

    cudaFuncSetAttribute(sage_fused_kernel,
                         cudaFuncAttributeMaxDynamicSharedMemorySize, SMEM_BYTES);

    detect_kernel<<<1, 1>>>(ei);

    // CSR build
    zero_deg_kernel<<<SCAN_BLOCKS, 256>>>();
    hist_kernel<<<EDGE_BLOCKS, 256>>>(ei);
    scan1_kernel<<<SCAN_BLOCKS, 256>>>();
    scan2_kernel<<<1, 256>>>();
    scan3_kernel<<<SCAN_BLOCKS, 256>>>();
    fill_kernel<<<EDGE_BLOCKS, 256>>>(ei);

    // Layer 1 (fused agg + GEMM + ReLU) -> g_h
    sage_fused_kernel<<<LINEAR_BLOCKS, 256, SMEM_BYTES>>>(
        x, W1, b1, nullptr, /*relu=*/1, /*from_gh=*/0, /*to_gh=*/1);
    // Layer 2 -> out
    sage_fused_kernel<<<LINEAR_BLOCKS, 256, SMEM_BYTES>>>(
        nullptr, W2, b2, out, /*relu=*/0, /*from_gh=*/1, /*to_gh=*/0);
}

// round 7
// speedup vs baseline: 3.3243x; 1.2535x over previous
#include <cuda_runtime.h>
#include <cstdint>

#define N_NODES 50000
#define N_EDGES 800000
#define F 64
#define TILE_M 128
#define ROW_STRIDE 132      // f32 stride of staged rows (conflict-free A frags)
#define WS_STRIDE 72        // float2 stride of W hi/lo (2-phase LDS.64)
#define SCAN_BLOCKS 196

// Scratch (allocation-free: __device__ globals)
__device__ int   g_deg[N_NODES];
__device__ int   g_off[N_NODES + 1];
__device__ int   g_cur[N_NODES];
__device__ int   g_csr[N_EDGES];
__device__ int   g_bsum[SCAN_BLOCKS];
__device__ float g_h[N_NODES * F];
__device__ float g_agg[N_NODES * F];
__device__ int   g_is64;

// ---------------------------------------------------------------------------
__global__ void detect_kernel(const void* __restrict__ ei) {
    const long long* p64 = (const long long*)ei;
    int ok = 1;
    #pragma unroll
    for (int i = 0; i < 16; i++) {
        long long v = p64[i];
        if (v < 0 || v >= N_NODES) ok = 0;
    }
    g_is64 = ok;
}

__device__ __forceinline__ int load_idx(const void* ei, int i, int is64) {
    if (is64) return (int)((const long long*)ei)[i];
    return ((const int*)ei)[i];
}

// ---------------------------------------------------------------------------
// CSR build: zero -> histogram -> 3-step scan -> fill  (proven in R6)
// ---------------------------------------------------------------------------
__global__ void zero_deg_kernel() {
    int i = blockIdx.x * blockDim.x + threadIdx.x;
    if (i < N_NODES) g_deg[i] = 0;
}

__global__ void hist_kernel(const void* __restrict__ ei) {
    int e = blockIdx.x * blockDim.x + threadIdx.x;
    if (e >= N_EDGES) return;
    int d = load_idx(ei, N_EDGES + e, g_is64);
    if ((unsigned)d < N_NODES) atomicAdd(&g_deg[d], 1);
}

__global__ void scan1_kernel() {
    __shared__ int sh[256];
    int t = threadIdx.x;
    int i = blockIdx.x * 256 + t;
    int v = (i < N_NODES) ? g_deg[i] : 0;
    sh[t] = v;
    __syncthreads();
    #pragma unroll
    for (int ofs = 1; ofs < 256; ofs <<= 1) {
        int add = (t >= ofs) ? sh[t - ofs] : 0;
        __syncthreads();
        sh[t] += add;
        __syncthreads();
    }
    if (i < N_NODES) g_off[i + 1] = sh[t];
    if (t == 255) g_bsum[blockIdx.x] = sh[255];
}

__global__ void scan2_kernel() {
    __shared__ int sh[256];
    int t = threadIdx.x;
    sh[t] = (t < SCAN_BLOCKS) ? g_bsum[t] : 0;
    __syncthreads();
    #pragma unroll
    for (int ofs = 1; ofs < 256; ofs <<= 1) {
        int add = (t >= ofs) ? sh[t - ofs] : 0;
        __syncthreads();
        sh[t] += add;
        __syncthreads();
    }
    if (t < SCAN_BLOCKS) g_bsum[t] = sh[t];
}

__global__ void scan3_kernel() {
    int t = threadIdx.x;
    int i = blockIdx.x * 256 + t;
    if (i < N_NODES) {
        if (blockIdx.x > 0) g_off[i + 1] += g_bsum[blockIdx.x - 1];
        g_cur[i] = 0;
    }
    if (i == 0) g_off[0] = 0;
}

__global__ void fill_kernel(const void* __restrict__ ei) {
    int e = blockIdx.x * blockDim.x + threadIdx.x;
    if (e >= N_EDGES) return;
    int is64 = g_is64;
    int s = load_idx(ei, e, is64);
    int d = load_idx(ei, N_EDGES + e, is64);
    if ((unsigned)s >= N_NODES || (unsigned)d >= N_NODES) return;
    int pos = atomicAdd(&g_cur[d], 1);
    g_csr[g_off[d] + pos] = s;
}

// ---------------------------------------------------------------------------
// CSR mean-aggregation -> g_agg. Warp per node (4 nodes/warp), float2/lane,
// unroll-4 for MLP. No smem -> high occupancy; gather L2-bound.
// ---------------------------------------------------------------------------
__global__ void __launch_bounds__(256)
agg_kernel(const float* __restrict__ xin) {
    int warp = threadIdx.x >> 5, lane = threadIdx.x & 31;
    const float2* xin2 = (const float2*)xin;
    #pragma unroll 1
    for (int i = 0; i < 4; i++) {
        int n = blockIdx.x * 32 + warp * 4 + i;
        if (n >= N_NODES) continue;
        int e0 = g_off[n], e1 = g_off[n + 1];
        float ax = 0.f, ay = 0.f;
        int e = e0;
        for (; e + 4 <= e1; e += 4) {
            int s0 = g_csr[e], s1 = g_csr[e + 1];
            int s2 = g_csr[e + 2], s3 = g_csr[e + 3];
            float2 v0 = xin2[s0 * 32 + lane];
            float2 v1 = xin2[s1 * 32 + lane];
            float2 v2 = xin2[s2 * 32 + lane];
            float2 v3 = xin2[s3 * 32 + lane];
            ax += v0.x + v1.x + v2.x + v3.x;
            ay += v0.y + v1.y + v2.y + v3.y;
        }
        for (; e < e1; e++) {
            float2 v = xin2[g_csr[e] * 32 + lane];
            ax += v.x; ay += v.y;
        }
        float inv = 1.0f / fmaxf((float)(e1 - e0), 1.0f);
        ((float2*)g_agg)[n * 32 + lane] = make_float2(ax * inv, ay * inv);
    }
}

// ---------------------------------------------------------------------------
// Tensor-core GEMM (3xTF32, fp32-accurate): out = [x || agg] @ W + b (+ReLU)
// Block 256 thr = 8 warps, TILE_M=128 nodes, N=64, K=128.
// Warp w owns rows [w*16, w*16+16); 8 n-tiles of m16n8k8; 16 k-steps.
// ---------------------------------------------------------------------------
__device__ __forceinline__ unsigned tf32_hi(float a) {
    unsigned r;
    asm("cvt.rna.tf32.f32 %0, %1;" : "=r"(r) : "f"(a));
    return r;
}

__device__ __forceinline__ void mma_tf32(float* c, unsigned a0, unsigned a1,
                                         unsigned a2, unsigned a3,
                                         unsigned b0, unsigned b1) {
    asm volatile(
        "mma.sync.aligned.m16n8k8.row.col.f32.tf32.tf32.f32 "
        "{%0,%1,%2,%3}, {%4,%5,%6,%7}, {%8,%9}, {%0,%1,%2,%3};"
        : "+f"(c[0]), "+f"(c[1]), "+f"(c[2]), "+f"(c[3])
        : "r"(a0), "r"(a1), "r"(a2), "r"(a3), "r"(b0), "r"(b1));
}

__global__ void __launch_bounds__(256)
gemm_kernel(const float* __restrict__ xin, const float* __restrict__ W,
            const float* __restrict__ bias, float* __restrict__ out, int relu) {
    extern __shared__ float sm[];
    float*  row = sm;                                   // [128][132] f32
    float2* Ws2 = (float2*)(sm + TILE_M * ROW_STRIDE);  // [128][72] (hi,lo)

    int tid = threadIdx.x;

    // Stage W split hi/lo (3xTF32 precompute).
    #pragma unroll
    for (int i = 0; i < 32; i++) {
        int idx = tid + i * 256;         // 0..8191
        int k = idx >> 6, c = idx & 63;
        float w = W[idx];
        unsigned hb = tf32_hi(w);
        float hf = __uint_as_float(hb);
        float lo = w - hf;
        unsigned lb = tf32_hi(lo);
        Ws2[k * WS_STRIDE + c] = make_float2(hf, __uint_as_float(lb));
    }

    // Stage rows: [x(64) || agg(64)] per node, row-major, stride 132.
    int base = blockIdx.x * TILE_M;
    #pragma unroll
    for (int i = 0; i < 8; i++) {
        int idx = tid + i * 256;         // 0..2047
        int nl = idx >> 4, q = idx & 15;
        int n = base + nl;
        int nc = n < N_NODES ? n : N_NODES - 1;
        float4 xv = ((const float4*)xin)[nc * 16 + q];
        *(float4*)&row[nl * ROW_STRIDE + q * 4] = xv;
        float4 av = ((const float4*)g_agg)[nc * 16 + q];
        *(float4*)&row[nl * ROW_STRIDE + 64 + q * 4] = av;
    }
    __syncthreads();

    int warp = tid >> 5, lane = tid & 31;
    int g = lane >> 2, t = lane & 3;
    int r0 = warp * 16 + g;              // fragment row (and +8)

    // Accumulators: 8 n-tiles x 4 regs; init with bias.
    float acc[8][4];
    #pragma unroll
    for (int nt = 0; nt < 8; nt++) {
        float2 bv = ((const float2*)bias)[nt * 4 + t];
        acc[nt][0] = bv.x; acc[nt][1] = bv.y;
        acc[nt][2] = bv.x; acc[nt][3] = bv.y;
    }

    #pragma unroll 2
    for (int ks = 0; ks < 16; ks++) {
        int k0 = ks * 8;
        // A fragment (m16 x k8, row-major): a0:(g,t) a1:(g+8,t) a2:(g,t+4) a3:(g+8,t+4)
        float a0f = row[r0 * ROW_STRIDE + k0 + t];
        float a1f = row[(r0 + 8) * ROW_STRIDE + k0 + t];
        float a2f = row[r0 * ROW_STRIDE + k0 + t + 4];
        float a3f = row[(r0 + 8) * ROW_STRIDE + k0 + t + 4];
        unsigned ah0 = tf32_hi(a0f), ah1 = tf32_hi(a1f);
        unsigned ah2 = tf32_hi(a2f), ah3 = tf32_hi(a3f);
        unsigned al0 = tf32_hi(a0f - __uint_as_float(ah0));
        unsigned al1 = tf32_hi(a1f - __uint_as_float(ah1));
        unsigned al2 = tf32_hi(a2f - __uint_as_float(ah2));
        unsigned al3 = tf32_hi(a3f - __uint_as_float(ah3));

        #pragma unroll
        for (int nt = 0; nt < 8; nt++) {
            // B fragment (k8 x n8, col-major): b0:(t, g) b1:(t+4, g)
            float2 w0 = Ws2[(k0 + t)     * WS_STRIDE + nt * 8 + g];
            float2 w1 = Ws2[(k0 + t + 4) * WS_STRIDE + nt * 8 + g];
            unsigned bh0 = __float_as_uint(w0.x), bl0 = __float_as_uint(w0.y);
            unsigned bh1 = __float_as_uint(w1.x), bl1 = __float_as_uint(w1.y);
            mma_tf32(acc[nt], ah0, ah1, ah2, ah3, bh0, bh1);  // hi*hi
            mma_tf32(acc[nt], ah0, ah1, ah2, ah3, bl0, bl1);  // hi*lo
            mma_tf32(acc[nt], al0, al1, al2, al3, bh0, bh1);  // lo*hi
        }
    }

    // Epilogue: ReLU + store. c0:(g,2t) c1:(g,2t+1) c2:(g+8,2t) c3:(g+8,2t+1)
    int n0 = base + r0;
    int n1 = n0 + 8;
    float2* out2 = (float2*)out;
    #pragma unroll
    for (int nt = 0; nt < 8; nt++) {
        float c0 = acc[nt][0], c1 = acc[nt][1];
        float c2 = acc[nt][2], c3 = acc[nt][3];
        if (relu) {
            c0 = fmaxf(c0, 0.f); c1 = fmaxf(c1, 0.f);
            c2 = fmaxf(c2, 0.f); c3 = fmaxf(c3, 0.f);
        }
        int colp = nt * 4 + t;           // float2 index within row (64/2=32)
        if (n0 < N_NODES) out2[n0 * 32 + colp] = make_float2(c0, c1);
        if (n1 < N_NODES) out2[n1 * 32 + colp] = make_float2(c2, c3);
    }
}

// ---------------------------------------------------------------------------
extern "C" void kernel_launch(void* const* d_in, const int* in_sizes, int n_in,
                              void* d_out, int out_size) {
    const float* x   = (const float*)d_in[0];
    const void*  ei  = d_in[1];
    const float* W1  = (const float*)d_in[2];
    const float* b1  = (const float*)d_in[3];
    const float* W2  = (const float*)d_in[4];
    const float* b2  = (const float*)d_in[5];
    float*       out = (float*)d_out;

    float* hbuf = nullptr;
    cudaGetSymbolAddress((void**)&hbuf, g_h);

    const int EDGE_BLOCKS = (N_EDGES + 255) / 256;               // 3125
    const int AGG_BLOCKS  = (N_NODES + 31) / 32;                 // 1563
    const int GEMM_BLOCKS = (N_NODES + TILE_M - 1) / TILE_M;     // 391
    const int SMEM_BYTES  = (TILE_M * ROW_STRIDE) * 4 + 128 * WS_STRIDE * 8; // 141312

    cudaFuncSetAttribute(gemm_kernel,
                         cudaFuncAttributeMaxDynamicSharedMemorySize, SMEM_BYTES);

    detect_kernel<<<1, 1>>>(ei);

    // CSR build
    zero_deg_kernel<<<SCAN_BLOCKS, 256>>>();
    hist_kernel<<<EDGE_BLOCKS, 256>>>(ei);
    scan1_kernel<<<SCAN_BLOCKS, 256>>>();
    scan2_kernel<<<1, 256>>>();
    scan3_kernel<<<SCAN_BLOCKS, 256>>>();
    fill_kernel<<<EDGE_BLOCKS, 256>>>(ei);

    // Layer 1
    agg_kernel<<<AGG_BLOCKS, 256>>>(x);
    gemm_kernel<<<GEMM_BLOCKS, 256, SMEM_BYTES>>>(x, W1, b1, hbuf, /*relu=*/1);
    // Layer 2
    agg_kernel<<<AGG_BLOCKS, 256>>>(hbuf);
    gemm_kernel<<<GEMM_BLOCKS, 256, SMEM_BYTES>>>(hbuf, W2, b2, out, /*relu=*/0);
}